// round 1
// baseline (speedup 1.0000x reference)
#include <cuda_runtime.h>
#include <cuda_fp16.h>
#include <cstdint>

// Problem shape (fixed): x [8,2048,2048] -> N=16384 tokens, D=2048, R=256
namespace {
constexpr int NTOK = 16384;
constexpr int DDIM = 2048;
constexpr int RDIM = 256;
}

// Scratch: __device__ globals (no allocation allowed in kernel_launch)
__device__ __align__(16) __half g_x16[NTOK * DDIM];   // 64 MB: x cast to fp16
__device__ __align__(16) __half g_win[DDIM * RDIM];   // 1 MB: sparsified+scaled W_in (fp16)
__device__ __align__(16) __half g_wout[RDIM * DDIM];  // 1 MB: sparsified+scaled W_out (fp16)
__device__ __align__(16) __half g_h[NTOK * RDIM];     // 8 MB: hidden (fp16, post-bias cast)

__device__ __forceinline__ uint32_t smem_u32(const void* p) {
    return (uint32_t)__cvta_generic_to_shared(p);
}

__device__ __forceinline__ void cp_async16(uint32_t dst, const void* src) {
    asm volatile("cp.async.cg.shared.global [%0], [%1], 16;\n" :: "r"(dst), "l"(src));
}
__device__ __forceinline__ void cp_commit() { asm volatile("cp.async.commit_group;\n"); }
__device__ __forceinline__ void cp_wait0()  { asm volatile("cp.async.wait_group 0;\n"); }

__device__ __forceinline__ void ldsm_x4(uint32_t addr, uint32_t& r0, uint32_t& r1,
                                        uint32_t& r2, uint32_t& r3) {
    asm volatile("ldmatrix.sync.aligned.m8n8.x4.shared.b16 {%0,%1,%2,%3}, [%4];\n"
                 : "=r"(r0), "=r"(r1), "=r"(r2), "=r"(r3) : "r"(addr));
}
__device__ __forceinline__ void ldsm_x4_t(uint32_t addr, uint32_t& r0, uint32_t& r1,
                                          uint32_t& r2, uint32_t& r3) {
    asm volatile("ldmatrix.sync.aligned.m8n8.x4.trans.shared.b16 {%0,%1,%2,%3}, [%4];\n"
                 : "=r"(r0), "=r"(r1), "=r"(r2), "=r"(r3) : "r"(addr));
}

__device__ __forceinline__ void mma16816(float* c, const uint32_t* a, uint32_t b0, uint32_t b1) {
    asm volatile(
        "mma.sync.aligned.m16n8k16.row.col.f32.f16.f16.f32 "
        "{%0,%1,%2,%3}, {%4,%5,%6,%7}, {%8,%9}, {%0,%1,%2,%3};\n"
        : "+f"(c[0]), "+f"(c[1]), "+f"(c[2]), "+f"(c[3])
        : "r"(a[0]), "r"(a[1]), "r"(a[2]), "r"(a[3]), "r"(b0), "r"(b1));
}

// ---------------------------------------------------------------------------
// Weight prep: 2:4 soft-threshold along the last dim, * scale, cast fp16.
// Group of 4 contiguous elements; t = 2nd-smallest |w| (= 3rd-largest).
// ---------------------------------------------------------------------------
template <int WHICH>  // 0 -> g_win (from weight_in), 1 -> g_wout (from weight_out)
__global__ void prep_weight_kernel(const float* __restrict__ w,
                                   const float* __restrict__ scale) {
    constexpr int ngroups = (DDIM * RDIM) / 4;  // same for both layers
    int g = blockIdx.x * blockDim.x + threadIdx.x;
    if (g >= ngroups) return;
    float4 v = reinterpret_cast<const float4*>(w)[g];
    float s = scale[0];
    float a0 = fabsf(v.x), a1 = fabsf(v.y), a2 = fabsf(v.z), a3 = fabsf(v.w);
    float lo1 = fminf(a0, a1), hi1 = fmaxf(a0, a1);
    float lo2 = fminf(a2, a3), hi2 = fmaxf(a2, a3);
    float t = fminf(fmaxf(lo1, lo2), fminf(hi1, hi2));  // 2nd smallest of 4
    float r0 = copysignf(fmaxf(a0 - t, 0.0f), v.x) * s;
    float r1 = copysignf(fmaxf(a1 - t, 0.0f), v.y) * s;
    float r2 = copysignf(fmaxf(a2 - t, 0.0f), v.z) * s;
    float r3 = copysignf(fmaxf(a3 - t, 0.0f), v.w) * s;
    __half2 h01 = __floats2half2_rn(r0, r1);
    __half2 h23 = __floats2half2_rn(r2, r3);
    uint2 pk;
    pk.x = *reinterpret_cast<uint32_t*>(&h01);
    pk.y = *reinterpret_cast<uint32_t*>(&h23);
    __half* out = (WHICH == 0) ? g_win : g_wout;
    reinterpret_cast<uint2*>(out)[g] = pk;
}

// ---------------------------------------------------------------------------
// x fp32 -> fp16 (matches reference's operand cast before the first matmul)
// ---------------------------------------------------------------------------
__global__ void convert_x_kernel(const float* __restrict__ x) {
    constexpr int n8 = (NTOK * DDIM) / 8;
    int i = blockIdx.x * blockDim.x + threadIdx.x;
    if (i >= n8) return;
    float4 v0 = reinterpret_cast<const float4*>(x)[2 * i];
    float4 v1 = reinterpret_cast<const float4*>(x)[2 * i + 1];
    __half2 h0 = __floats2half2_rn(v0.x, v0.y);
    __half2 h1 = __floats2half2_rn(v0.z, v0.w);
    __half2 h2 = __floats2half2_rn(v1.x, v1.y);
    __half2 h3 = __floats2half2_rn(v1.z, v1.w);
    uint4 pk;
    pk.x = *reinterpret_cast<uint32_t*>(&h0);
    pk.y = *reinterpret_cast<uint32_t*>(&h1);
    pk.z = *reinterpret_cast<uint32_t*>(&h2);
    pk.w = *reinterpret_cast<uint32_t*>(&h3);
    reinterpret_cast<uint4*>(g_x16)[i] = pk;
}

// ---------------------------------------------------------------------------
// GEMM: C[N,M] = A[N,K](fp16) @ B[K,M](fp16) + bias, fp32 accumulate.
// LAYER 0: A=g_x16, B=g_win, K=2048, M=256, out -> g_h as fp16
// LAYER 1: A=g_h,   B=g_wout, K=256, M=2048, out -> Cout as fp32
// CTA tile 128x128x32, 8 warps in 2(M)x4(N), warp tile 64x32,
// mma.sync m16n8k16, cp.async double buffered.
// ---------------------------------------------------------------------------
template <int LAYER>
__global__ __launch_bounds__(256)
void gemm_kernel(const float* __restrict__ bias, float* __restrict__ Cout) {
    constexpr int K = (LAYER == 0) ? DDIM : RDIM;
    constexpr int M = (LAYER == 0) ? RDIM : DDIM;
    constexpr int BM = 128, BN = 128, BK = 32;
    constexpr int SA = BK + 8;   // 40 halves = 80B row stride (16B aligned)
    constexpr int SB = BN + 8;   // 136 halves = 272B row stride (16B aligned)

    __shared__ __half As[2][BM * SA];
    __shared__ __half Bs[2][BK * SB];

    const __half* A = (LAYER == 0) ? g_x16 : g_h;
    const __half* B = (LAYER == 0) ? g_win : g_wout;

    const int tid = threadIdx.x;
    const int lane = tid & 31;
    const int wid = tid >> 5;
    const int warp_m = wid & 1;   // 0..1
    const int warp_n = wid >> 1;  // 0..3
    const int bm = blockIdx.y * BM;
    const int bn = blockIdx.x * BN;

    float acc[4][4][4];
#pragma unroll
    for (int i = 0; i < 4; ++i)
#pragma unroll
        for (int j = 0; j < 4; ++j)
#pragma unroll
            for (int k = 0; k < 4; ++k) acc[i][j][k] = 0.0f;

    // Global->shared load mapping: 16B per cp.async
    const int a_row = tid >> 2;          // 0..63 (two passes of 64 rows)
    const int a_col = (tid & 3) * 8;     // 0,8,16,24
    const int b_row = tid >> 4;          // 0..15 (two passes of 16 rows)
    const int b_col = (tid & 15) * 8;    // 0..120

    auto load_tile = [&](int kt, int buf) {
        const __half* Ag = A + (size_t)bm * K + kt * BK;
#pragma unroll
        for (int p = 0; p < 2; ++p) {
            int r = a_row + p * 64;
            cp_async16(smem_u32(&As[buf][r * SA + a_col]), Ag + (size_t)r * K + a_col);
        }
        const __half* Bg = B + (size_t)(kt * BK) * M + bn;
#pragma unroll
        for (int p = 0; p < 2; ++p) {
            int r = b_row + p * 16;
            cp_async16(smem_u32(&Bs[buf][r * SB + b_col]), Bg + (size_t)r * M + b_col);
        }
    };

    constexpr int KT = K / BK;
    load_tile(0, 0);
    cp_commit();
    cp_wait0();
    __syncthreads();

    for (int kt = 0; kt < KT; ++kt) {
        const int buf = kt & 1;
        if (kt + 1 < KT) { load_tile(kt + 1, buf ^ 1); cp_commit(); }

#pragma unroll
        for (int ks = 0; ks < 2; ++ks) {
            const int k0 = ks * 16;
            uint32_t afr[4][4];
#pragma unroll
            for (int mi = 0; mi < 4; ++mi) {
                uint32_t addr = smem_u32(
                    &As[buf][(warp_m * 64 + mi * 16 + (lane & 15)) * SA + k0 + (lane >> 4) * 8]);
                ldsm_x4(addr, afr[mi][0], afr[mi][1], afr[mi][2], afr[mi][3]);
            }
            uint32_t bfr[2][4];
#pragma unroll
            for (int np = 0; np < 2; ++np) {
                const int n0 = warp_n * 32 + np * 16;
                uint32_t addr = smem_u32(
                    &Bs[buf][(k0 + (lane & 15)) * SB + n0 + (lane >> 4) * 8]);
                ldsm_x4_t(addr, bfr[np][0], bfr[np][1], bfr[np][2], bfr[np][3]);
            }
#pragma unroll
            for (int mi = 0; mi < 4; ++mi)
#pragma unroll
                for (int ni = 0; ni < 4; ++ni)
                    mma16816(acc[mi][ni], afr[mi],
                             bfr[ni >> 1][(ni & 1) * 2], bfr[ni >> 1][(ni & 1) * 2 + 1]);
        }

        if (kt + 1 < KT) { cp_wait0(); __syncthreads(); }
    }

    // Epilogue: + bias, write fp16 (layer 0, to g_h) or fp32 (layer 1, to Cout)
    const int row0 = bm + warp_m * 64;
    const int col0 = bn + warp_n * 32;
#pragma unroll
    for (int mi = 0; mi < 4; ++mi) {
#pragma unroll
        for (int ni = 0; ni < 4; ++ni) {
            const int r = row0 + mi * 16 + (lane >> 2);
            const int c = col0 + ni * 8 + (lane & 3) * 2;
            const float bb0 = bias[c];
            const float bb1 = bias[c + 1];
            const float v00 = acc[mi][ni][0] + bb0;
            const float v01 = acc[mi][ni][1] + bb1;
            const float v10 = acc[mi][ni][2] + bb0;
            const float v11 = acc[mi][ni][3] + bb1;
            if (LAYER == 0) {
                __half2* H = reinterpret_cast<__half2*>(g_h);
                H[((size_t)r * M + c) >> 1]       = __floats2half2_rn(v00, v01);
                H[((size_t)(r + 8) * M + c) >> 1] = __floats2half2_rn(v10, v11);
            } else {
                float2* F = reinterpret_cast<float2*>(Cout);
                F[((size_t)r * M + c) >> 1]       = make_float2(v00, v01);
                F[((size_t)(r + 8) * M + c) >> 1] = make_float2(v10, v11);
            }
        }
    }
}

// ---------------------------------------------------------------------------
// kernel_launch
// inputs (metadata order): x, weight_in, weight_out, bias_in, bias_out,
//                          sparse_scale_in, sparse_scale_out
// ---------------------------------------------------------------------------
extern "C" void kernel_launch(void* const* d_in, const int* in_sizes, int n_in,
                              void* d_out, int out_size) {
    const float* x     = (const float*)d_in[0];
    const float* w_in  = (const float*)d_in[1];
    const float* w_out = (const float*)d_in[2];
    const float* b_in  = (const float*)d_in[3];
    const float* b_out = (const float*)d_in[4];
    const float* s_in  = (const float*)d_in[5];
    const float* s_out = (const float*)d_in[6];
    float* y = (float*)d_out;

    constexpr int ngroups = (DDIM * RDIM) / 4;        // 131072
    prep_weight_kernel<0><<<(ngroups + 255) / 256, 256>>>(w_in, s_in);
    prep_weight_kernel<1><<<(ngroups + 255) / 256, 256>>>(w_out, s_out);

    constexpr int n8 = (NTOK * DDIM) / 8;             // 4194304
    convert_x_kernel<<<(n8 + 255) / 256, 256>>>(x);

    dim3 g1(RDIM / 128, NTOK / 128);                   // (2, 128)
    gemm_kernel<0><<<g1, 256>>>(b_in, nullptr);

    dim3 g2(DDIM / 128, NTOK / 128);                   // (16, 128)
    gemm_kernel<1><<<g2, 256>>>(b_out, y);
}

// round 3
// speedup vs baseline: 1.0385x; 1.0385x over previous
#include <cuda_runtime.h>
#include <cuda_fp16.h>
#include <cstdint>

namespace {
constexpr int NTOK = 16384;
constexpr int DDIM = 2048;
constexpr int RDIM = 256;
}

// Scratch (__device__ globals; no allocation allowed)
__device__ __align__(16) __half g_win[(size_t)DDIM * RDIM];   // W_in sparsified fp16 [K=D, M=R]
__device__ __align__(16) __half g_wout[(size_t)RDIM * DDIM];  // W_out sparsified fp16 [K=R, M=D]
__device__ __align__(16) __half g_h[(size_t)NTOK * RDIM];     // hidden fp16 [N, R]

__device__ __forceinline__ uint32_t smem_u32(const void* p) {
    return (uint32_t)__cvta_generic_to_shared(p);
}
__device__ __forceinline__ void cp_async16(uint32_t dst, const void* src) {
    asm volatile("cp.async.cg.shared.global [%0], [%1], 16;\n" :: "r"(dst), "l"(src));
}
__device__ __forceinline__ void cp_commit() { asm volatile("cp.async.commit_group;\n" ::: "memory"); }
template <int N>
__device__ __forceinline__ void cp_wait() {
    asm volatile("cp.async.wait_group %0;\n" :: "n"(N) : "memory");
}
__device__ __forceinline__ void ldsm_x4(uint32_t addr, uint32_t& r0, uint32_t& r1,
                                        uint32_t& r2, uint32_t& r3) {
    asm volatile("ldmatrix.sync.aligned.m8n8.x4.shared.b16 {%0,%1,%2,%3}, [%4];\n"
                 : "=r"(r0), "=r"(r1), "=r"(r2), "=r"(r3) : "r"(addr));
}
__device__ __forceinline__ void ldsm_x4_t(uint32_t addr, uint32_t& r0, uint32_t& r1,
                                          uint32_t& r2, uint32_t& r3) {
    asm volatile("ldmatrix.sync.aligned.m8n8.x4.trans.shared.b16 {%0,%1,%2,%3}, [%4];\n"
                 : "=r"(r0), "=r"(r1), "=r"(r2), "=r"(r3) : "r"(addr));
}
__device__ __forceinline__ void mma16816(float* c, const uint32_t* a, uint32_t b0, uint32_t b1) {
    asm volatile(
        "mma.sync.aligned.m16n8k16.row.col.f32.f16.f16.f32 "
        "{%0,%1,%2,%3}, {%4,%5,%6,%7}, {%8,%9}, {%0,%1,%2,%3};\n"
        : "+f"(c[0]), "+f"(c[1]), "+f"(c[2]), "+f"(c[3])
        : "r"(a[0]), "r"(a[1]), "r"(a[2]), "r"(a[3]), "r"(b0), "r"(b1));
}

// ---------------------------------------------------------------------------
// Weight prep: 2:4 soft-threshold along last dim, * scale, cast fp16.
// Output layout == input layout ([K, M] M-major for the GEMM's B operand).
// ---------------------------------------------------------------------------
template <int WHICH>
__global__ void prep_weight_kernel(const float* __restrict__ w,
                                   const float* __restrict__ scale) {
    constexpr int ngroups = (DDIM * RDIM) / 4;
    int g = blockIdx.x * blockDim.x + threadIdx.x;
    if (g >= ngroups) return;
    float4 v = reinterpret_cast<const float4*>(w)[g];
    float s = scale[0];
    float a0 = fabsf(v.x), a1 = fabsf(v.y), a2 = fabsf(v.z), a3 = fabsf(v.w);
    float lo1 = fminf(a0, a1), hi1 = fmaxf(a0, a1);
    float lo2 = fminf(a2, a3), hi2 = fmaxf(a2, a3);
    float t = fminf(fmaxf(lo1, lo2), fminf(hi1, hi2));  // 2nd smallest of 4
    float r0 = copysignf(fmaxf(a0 - t, 0.0f), v.x) * s;
    float r1 = copysignf(fmaxf(a1 - t, 0.0f), v.y) * s;
    float r2 = copysignf(fmaxf(a2 - t, 0.0f), v.z) * s;
    float r3 = copysignf(fmaxf(a3 - t, 0.0f), v.w) * s;
    __half2 h01 = __floats2half2_rn(r0, r1);
    __half2 h23 = __floats2half2_rn(r2, r3);
    uint2 pk;
    pk.x = *reinterpret_cast<uint32_t*>(&h01);
    pk.y = *reinterpret_cast<uint32_t*>(&h23);
    __half* out = (WHICH == 0) ? g_win : g_wout;
    reinterpret_cast<uint2*>(out)[g] = pk;
}

// ---------------------------------------------------------------------------
// GEMM: C[N,M] = A[N,K] @ B[K,M] + bias, fp32 accumulate, mma.sync m16n8k16.
// CTA tile 128x256xBK32, 8 warps as 2(M)x4(N) -> 64x64 warp tiles.
// LAYER 0: A = x fp32 (converted to fp16 on the fly), K=2048, M=256 -> g_h fp16
// LAYER 1: A = g_h fp16,                              K=256,  M=2048 -> y fp32
// B: 3-stage cp.async. A: LDG (issued before MMA block) -> cvt -> STS fp16.
// ---------------------------------------------------------------------------
template <int LAYER>
__global__ __launch_bounds__(256, 1)
void gemm_kernel(const float* __restrict__ Afp32, const float* __restrict__ bias,
                 float* __restrict__ Cout) {
    constexpr int K  = (LAYER == 0) ? DDIM : RDIM;
    constexpr int M  = (LAYER == 0) ? RDIM : DDIM;
    constexpr int BM = 128, BN = 256, BK = 32;
    constexpr int S  = 3;
    constexpr int KT = K / BK;
    constexpr int SA = BK + 8;    // 40 halves (80B rows)
    constexpr int SB = BN + 8;    // 264 halves (528B rows)
    constexpr int A_STAGE = BM * SA;  // halves
    constexpr int B_STAGE = BK * SB;  // halves

    extern __shared__ char dynsm[];
    __half* As   = reinterpret_cast<__half*>(dynsm);
    __half* Bs   = As + S * A_STAGE;
    float* biasS = reinterpret_cast<float*>(Bs + S * B_STAGE);

    const int tid  = threadIdx.x;
    const int lane = tid & 31;
    const int wid  = tid >> 5;
    const int wm   = wid & 1;   // 0..1 (64-row slabs)
    const int wn   = wid >> 1;  // 0..3 (64-col slabs)
    const int bm   = blockIdx.y * BM;
    const int bn   = blockIdx.x * BN;

    const __half* B = (LAYER == 0) ? g_win : g_wout;

    if (tid < BN) biasS[tid] = bias[bn + tid];

    float acc[4][8][4];
#pragma unroll
    for (int i = 0; i < 4; ++i)
#pragma unroll
        for (int j = 0; j < 8; ++j)
#pragma unroll
            for (int k = 0; k < 4; ++k) acc[i][j][k] = 0.0f;

    // --- B tile loader: 32 rows x 256 halves, 4 x cp.async16 per thread
    auto loadB = [&](int kt, int s) {
        const __half* Bg = B + (size_t)(kt * BK) * M + bn;
#pragma unroll
        for (int p = 0; p < 4; ++p) {
            int c = tid + p * 256;
            int row = c >> 5, col = (c & 31) * 8;
            cp_async16(smem_u32(&Bs[s * B_STAGE + row * SB + col]),
                       Bg + (size_t)row * M + col);
        }
    };

    // --- A loaders ---------------------------------------------------------
    // LAYER 0: thread owns row tid>>1, 16 fp32 cols at (tid&1)*16.
    // LAYER 1: thread owns 2 chunks of 8 halves.
    float4 a32[4];   // layer0 staging
    uint4  a16[2];   // layer1 staging

    auto ldgA = [&](int kt) {
        if (LAYER == 0) {
            const float* Ag = Afp32 + (size_t)(bm + (tid >> 1)) * K + kt * BK + (tid & 1) * 16;
#pragma unroll
            for (int p = 0; p < 4; ++p)
                a32[p] = reinterpret_cast<const float4*>(Ag)[p];
        } else {
            const __half* Ag = g_h + (size_t)bm * K + kt * BK;
#pragma unroll
            for (int p = 0; p < 2; ++p) {
                int c = tid + p * 256;
                int row = c >> 2, col = (c & 3) * 8;
                a16[p] = *reinterpret_cast<const uint4*>(Ag + (size_t)row * K + col);
            }
        }
    };
    auto stsA = [&](int s) {
        if (LAYER == 0) {
            __half h[16];
#pragma unroll
            for (int p = 0; p < 4; ++p) {
                h[p * 4 + 0] = __float2half_rn(a32[p].x);
                h[p * 4 + 1] = __float2half_rn(a32[p].y);
                h[p * 4 + 2] = __float2half_rn(a32[p].z);
                h[p * 4 + 3] = __float2half_rn(a32[p].w);
            }
            int row = tid >> 1, col = (tid & 1) * 16;
            *reinterpret_cast<uint4*>(&As[s * A_STAGE + row * SA + col]) =
                *reinterpret_cast<uint4*>(&h[0]);
            *reinterpret_cast<uint4*>(&As[s * A_STAGE + row * SA + col + 8]) =
                *reinterpret_cast<uint4*>(&h[8]);
        } else {
#pragma unroll
            for (int p = 0; p < 2; ++p) {
                int c = tid + p * 256;
                int row = c >> 2, col = (c & 3) * 8;
                *reinterpret_cast<uint4*>(&As[s * A_STAGE + row * SA + col]) = a16[p];
            }
        }
    };

    // --- prologue: fill stages 0..S-1 --------------------------------------
#pragma unroll
    for (int s = 0; s < S; ++s) {
        ldgA(s);
        stsA(s);
        loadB(s, s);
        cp_commit();
    }

    // --- main loop ----------------------------------------------------------
    for (int kt = 0; kt < KT; ++kt) {
        const int s = kt % S;
        const bool more = (kt + S < KT);
        cp_wait<S - 1>();
        __syncthreads();

        if (more) ldgA(kt + S);   // long-latency LDG issued before MMA block

#pragma unroll
        for (int ks = 0; ks < 2; ++ks) {
            const int k0 = ks * 16;
            uint32_t afr[4][4];
#pragma unroll
            for (int mi = 0; mi < 4; ++mi) {
                uint32_t addr = smem_u32(
                    &As[s * A_STAGE + (wm * 64 + mi * 16 + (lane & 15)) * SA + k0 + (lane >> 4) * 8]);
                ldsm_x4(addr, afr[mi][0], afr[mi][1], afr[mi][2], afr[mi][3]);
            }
            uint32_t bfr[4][4];
#pragma unroll
            for (int np = 0; np < 4; ++np) {
                uint32_t addr = smem_u32(
                    &Bs[s * B_STAGE + (k0 + (lane & 15)) * SB + wn * 64 + np * 16 + (lane >> 4) * 8]);
                ldsm_x4_t(addr, bfr[np][0], bfr[np][1], bfr[np][2], bfr[np][3]);
            }
#pragma unroll
            for (int mi = 0; mi < 4; ++mi)
#pragma unroll
                for (int ni = 0; ni < 8; ++ni)
                    mma16816(acc[mi][ni], afr[mi],
                             bfr[ni >> 1][(ni & 1) * 2], bfr[ni >> 1][(ni & 1) * 2 + 1]);
        }

        __syncthreads();   // everyone done reading stage s
        if (more) { stsA(s); loadB(kt + S, s); }
        cp_commit();        // (possibly empty) keeps wait_group counting uniform
    }

    // --- epilogue: + bias; layer0 -> g_h fp16, layer1 -> Cout fp32 ----------
    const int row0 = bm + wm * 64;
    const int col0 = wn * 64;
#pragma unroll
    for (int mi = 0; mi < 4; ++mi) {
#pragma unroll
        for (int ni = 0; ni < 8; ++ni) {
            const int r = row0 + mi * 16 + (lane >> 2);
            const int c = col0 + ni * 8 + (lane & 3) * 2;
            const float bb0 = biasS[c];
            const float bb1 = biasS[c + 1];
            const float v00 = acc[mi][ni][0] + bb0;
            const float v01 = acc[mi][ni][1] + bb1;
            const float v10 = acc[mi][ni][2] + bb0;
            const float v11 = acc[mi][ni][3] + bb1;
            const int gc = bn + c;
            if (LAYER == 0) {
                __half2* H = reinterpret_cast<__half2*>(g_h);
                H[((size_t)r * M + gc) >> 1]       = __floats2half2_rn(v00, v01);
                H[((size_t)(r + 8) * M + gc) >> 1] = __floats2half2_rn(v10, v11);
            } else {
                float2* F = reinterpret_cast<float2*>(Cout);
                F[((size_t)r * M + gc) >> 1]       = make_float2(v00, v01);
                F[((size_t)(r + 8) * M + gc) >> 1] = make_float2(v10, v11);
            }
        }
    }
}

// ---------------------------------------------------------------------------
// kernel_launch. inputs: x, weight_in, weight_out, bias_in, bias_out,
//                        sparse_scale_in, sparse_scale_out
// ---------------------------------------------------------------------------
extern "C" void kernel_launch(void* const* d_in, const int* in_sizes, int n_in,
                              void* d_out, int out_size) {
    const float* x     = (const float*)d_in[0];
    const float* w_in  = (const float*)d_in[1];
    const float* w_out = (const float*)d_in[2];
    const float* b_in  = (const float*)d_in[3];
    const float* b_out = (const float*)d_in[4];
    const float* s_in  = (const float*)d_in[5];
    const float* s_out = (const float*)d_in[6];
    float* y = (float*)d_out;

    constexpr int ngroups = (DDIM * RDIM) / 4;
    prep_weight_kernel<0><<<(ngroups + 255) / 256, 256>>>(w_in, s_in);
    prep_weight_kernel<1><<<(ngroups + 255) / 256, 256>>>(w_out, s_out);

    // dynamic smem: 3*(128*40 + 32*264)*2 + 256*4 bytes
    constexpr int SMEM_BYTES = 3 * (128 * 40 + 32 * 264) * 2 + 256 * 4;  // 82432
    cudaFuncSetAttribute(gemm_kernel<0>, cudaFuncAttributeMaxDynamicSharedMemorySize, SMEM_BYTES);
    cudaFuncSetAttribute(gemm_kernel<1>, cudaFuncAttributeMaxDynamicSharedMemorySize, SMEM_BYTES);

    dim3 g1(RDIM / 256, NTOK / 128);   // (1, 128)
    gemm_kernel<0><<<g1, 256, SMEM_BYTES>>>(x, b_in, nullptr);

    dim3 g2(DDIM / 256, NTOK / 128);   // (8, 128)
    gemm_kernel<1><<<g2, 256, SMEM_BYTES>>>(nullptr, b_out, y);
}